// round 15
// baseline (speedup 1.0000x reference)
#include <cuda_runtime.h>
#include <cuda_fp16.h>
#include <cstdint>

#define NN 2048
#define FF 64
#define HH 128
#define TI 32
#define NB (NN/TI)            // 64
#define NPAIR (NB*(NB+1)/2)   // 2080
#define EDGEF 2096128.0f      // NN*(NN-1)/2
#define ES ((size_t)NPAIR*1024)

typedef unsigned int u32;

// ---------------- scratch ----------------
__device__ float g_A1[NN*HH];
__device__ float g_A2[NN*HH];
__device__ float g_H3[NN*FF];
__device__ float g_W2f[HH*HH];
__device__ float g_b2f[HH];
__device__ float g_W3f[HH*FF];
__device__ float g_b3f[FF];
__device__ double g_s1[HH], g_q1[HH], g_s2[HH], g_q2[HH];
__device__ float g_s5[HH], g_q5[HH];
// t-cache, column-planar: g_Tc[c2*ES + slot], half2 per u32; invalid diag slots = 0
__device__ u32 g_Tc[64*ES];

__device__ __forceinline__ float lrelu(float x){ return fmaxf(x, 0.01f*x); }

// ---------------- init ----------------
__global__ void k_init(){
  int tid = threadIdx.x;
  if (tid < HH){
    g_s1[tid]=0.0; g_q1[tid]=0.0;
    g_s2[tid]=0.0; g_q2[tid]=0.0;
    g_s5[tid]=0.f; g_q5[tid]=0.f;
  }
}

// ---------------- node layer 1 ----------------
__global__ void k_node1(const float* __restrict__ nf, const float* __restrict__ W1,
                        const float* __restrict__ b1){
  __shared__ float nfs[8*FF];
  int tid = threadIdx.x;
  int r0  = blockIdx.x*8;
  for (int i = tid; i < 8*FF; i += 128) nfs[i] = nf[r0*FF + i];
  float w[FF];
  #pragma unroll
  for (int k = 0; k < FF; k++) w[k] = W1[k*HH + tid];
  float bc = b1[tid];
  __syncthreads();
  float s = 0.f, q = 0.f;
  #pragma unroll
  for (int r = 0; r < 8; r++){
    float a0=0.f, a1=0.f, a2=0.f, a3=0.f;
    #pragma unroll
    for (int k = 0; k < FF; k += 4){
      a0 += nfs[r*FF+k]*w[k];
      a1 += nfs[r*FF+k+1]*w[k+1];
      a2 += nfs[r*FF+k+2]*w[k+2];
      a3 += nfs[r*FF+k+3]*w[k+3];
    }
    float a = lrelu(bc + (a0+a1) + (a2+a3));
    g_A1[(r0+r)*HH + tid] = a;
    s += a; q += a*a;
  }
  atomicAdd(&g_s1[tid], (double)s);
  atomicAdd(&g_q1[tid], (double)q);
}

__global__ void k_fold1(const float* __restrict__ W2, const float* __restrict__ b2,
                        const float* __restrict__ g1, const float* __restrict__ be1){
  __shared__ float al[HH], bt[HH];
  int tid = threadIdx.x;
  double m = g_s1[tid]/(double)NN;
  double v = g_q1[tid]/(double)NN - m*m;
  float a = rsqrtf((float)v + 1e-5f) * g1[tid];
  al[tid] = a; bt[tid] = be1[tid] - (float)m*a;
  __syncthreads();
  float bb = b2[tid];
  for (int k = 0; k < HH; k++){
    float w = W2[k*HH + tid];
    g_W2f[k*HH + tid] = al[k]*w;
    bb += bt[k]*w;
  }
  g_b2f[tid] = bb;
}

// ---------------- node layer 2 ----------------
__global__ void k_node2(){
  extern __shared__ float sm2[];
  float* w2s = sm2;                 // 16384
  float* a1s = sm2 + HH*HH;         // 1024
  int tid = threadIdx.x;
  int r0  = blockIdx.x*8;
  for (int i = tid; i < HH*HH; i += 128) w2s[i] = g_W2f[i];
  for (int i = tid; i < 8*HH; i += 128) a1s[i] = g_A1[r0*HH + i];
  float bc = g_b2f[tid];
  __syncthreads();
  float acc[8];
  #pragma unroll
  for (int r = 0; r < 8; r++) acc[r] = 0.f;
  for (int kb = 0; kb < HH; kb += 8){
    float w0 = w2s[(kb+0)*HH+tid], w1 = w2s[(kb+1)*HH+tid];
    float w2 = w2s[(kb+2)*HH+tid], w3 = w2s[(kb+3)*HH+tid];
    float w4 = w2s[(kb+4)*HH+tid], w5 = w2s[(kb+5)*HH+tid];
    float w6 = w2s[(kb+6)*HH+tid], w7 = w2s[(kb+7)*HH+tid];
    #pragma unroll
    for (int r = 0; r < 8; r++){
      const float* ar = a1s + r*HH + kb;
      float p0 = ar[0]*w0 + ar[1]*w1;
      float p1 = ar[2]*w2 + ar[3]*w3;
      float p2 = ar[4]*w4 + ar[5]*w5;
      float p3 = ar[6]*w6 + ar[7]*w7;
      acc[r] += (p0+p1) + (p2+p3);
    }
  }
  float s = 0.f, q = 0.f;
  #pragma unroll
  for (int r = 0; r < 8; r++){
    float a = lrelu(acc[r] + bc);
    g_A2[(r0+r)*HH + tid] = a;
    s += a; q += a*a;
  }
  atomicAdd(&g_s2[tid], (double)s);
  atomicAdd(&g_q2[tid], (double)q);
}

__global__ void k_fold2(const float* __restrict__ W3, const float* __restrict__ b3,
                        const float* __restrict__ g2, const float* __restrict__ be2){
  __shared__ float al[HH], bt[HH];
  int tid = threadIdx.x;
  double m = g_s2[tid]/(double)NN;
  double v = g_q2[tid]/(double)NN - m*m;
  float a = rsqrtf((float)v + 1e-5f) * g2[tid];
  al[tid] = a; bt[tid] = be2[tid] - (float)m*a;
  __syncthreads();
  if (tid < FF){
    float bb = b3[tid];
    for (int k = 0; k < HH; k++){
      float w = W3[k*FF + tid];
      g_W3f[k*FF + tid] = al[k]*w;
      bb += bt[k]*w;
    }
    g_b3f[tid] = bb;
  }
}

// ---------------- node layer 3 ----------------
__global__ void k_node3(const float* __restrict__ nf){
  __shared__ float a2s[8*HH];     // 4KB
  __shared__ float w3s[HH*FF];    // 32KB
  int tid = threadIdx.x;
  int r0  = blockIdx.x*8;
  for (int i = tid; i < 8*HH; i += 128) a2s[i] = g_A2[r0*HH + i];
  for (int i = tid; i < HH*FF; i += 128) w3s[i] = g_W3f[i];
  __syncthreads();
  int c = tid & 63, rh = tid >> 6;
  float acc[4];
  #pragma unroll
  for (int r = 0; r < 4; r++) acc[r] = 0.f;
  for (int kb = 0; kb < HH; kb += 8){
    float w0 = w3s[(kb+0)*FF+c], w1 = w3s[(kb+1)*FF+c];
    float w2 = w3s[(kb+2)*FF+c], w3 = w3s[(kb+3)*FF+c];
    float w4 = w3s[(kb+4)*FF+c], w5 = w3s[(kb+5)*FF+c];
    float w6 = w3s[(kb+6)*FF+c], w7 = w3s[(kb+7)*FF+c];
    #pragma unroll
    for (int r = 0; r < 4; r++){
      const float* ar = a2s + (rh*4+r)*HH + kb;
      float p0 = ar[0]*w0 + ar[1]*w1;
      float p1 = ar[2]*w2 + ar[3]*w3;
      float p2 = ar[4]*w4 + ar[5]*w5;
      float p3 = ar[6]*w6 + ar[7]*w7;
      acc[r] += (p0+p1) + (p2+p3);
    }
  }
  #pragma unroll
  for (int r = 0; r < 4; r++){
    int rr = rh*4 + r;
    g_H3[(r0+rr)*FF + c] = acc[r] + g_b3f[c] + nf[(r0+rr)*FF + c];
  }
}

// ---------------- edge pass 1: fp16 mma, hoisted B-fragments, mh-split, no stats ----------------
#define H_STR   72
#define OFF_W5F 0
#define OFF_HI  5120
#define OFF_HJ  (OFF_HI+2304)
#define OFF_B5  (OFF_HJ+2304)
#define EDGE1_SMEM ((OFF_B5 + 128)*4)   // 39424 bytes

__global__ void __launch_bounds__(256, 2)
k_edgeG(const float* __restrict__ W5, const float* __restrict__ b5){
  extern __shared__ float sm[];
  u32*   w5f = (u32*)(sm + OFF_W5F);      // fragment-order B, lane stride 20 u32
  float* Hi  = sm + OFF_HI;
  float* Hj  = sm + OFF_HJ;
  float* b5s = sm + OFF_B5;

  int tid = threadIdx.x;
  int lane = tid & 31, wid = tid >> 5;
  int mg = wid & 3, ng = wid >> 2;
  int qid = lane >> 2, qlane = lane & 3;

  int p = blockIdx.x, bi = 0, rem = p;
  while (rem >= NB - bi){ rem -= NB - bi; bi++; }
  int bj = bi + rem;

  for (int idx = tid; idx < 4096; idx += 256){
    int g  = idx >> 11;
    int ks = (idx >> 9) & 3;
    int ln = (idx >> 4) & 31;
    int f  = idx & 15;
    int qi = ln >> 2, ql = ln & 3;
    int nt = f >> 1, w = f & 1;
    int k = ks*16 + ql*2 + w*8;
    int n = g*64 + nt*8 + qi;
    __half2 hv = __floats2half2_rn(W5[k*HH + n], W5[(k+1)*HH + n]);
    w5f[((g*4 + ks)*32 + ln)*20 + f] = *(u32*)&hv;
  }
  for (int i = tid; i < TI*FF; i += 256){
    int r = i >> 6, k = i & 63;
    Hi[r*H_STR + k] = g_H3[(bi*TI + r)*FF + k];
    Hj[r*H_STR + k] = g_H3[(bj*TI + r)*FF + k];
  }
  if (tid < HH) b5s[tid] = b5[tid];
  __syncthreads();

  // hoist B fragments to registers: 16 uint4 = 64 regs, loop-invariant
  uint4 Breg[4][4];
  #pragma unroll
  for (int ks = 0; ks < 4; ks++){
    const uint4* Bp = (const uint4*)(w5f + ((ng*4 + ks)*32 + lane)*20);
    Breg[ks][0] = Bp[0]; Breg[ks][1] = Bp[1];
    Breg[ks][2] = Bp[2]; Breg[ks][3] = Bp[3];
  }

  size_t pbase = (size_t)p*1024;
  bool offdiag = (bi != bj);

  for (int t = 0; t < 8; t++){
    int ii = t*4 + mg;
    const float2* HiR = (const float2*)(Hi + ii*H_STR);
    size_t tbase = pbase + (size_t)t*128 + mg*32;

    #pragma unroll
    for (int mh = 0; mh < 2; mh++){
      float acc[8][4];
      #pragma unroll
      for (int nt = 0; nt < 8; nt++)
        #pragma unroll
        for (int c = 0; c < 4; c++) acc[nt][c] = 0.f;

      const float2* HjA = (const float2*)(Hj + (mh*16 + qid)*H_STR);
      const float2* HjB = (const float2*)(Hj + (mh*16 + qid + 8)*H_STR);

      #pragma unroll
      for (int ks = 0; ks < 4; ks++){
        const u32* b = (const u32*)&Breg[ks][0];
        int c2 = ks*8 + qlane;
        float2 hiA = HiR[c2], hiB = HiR[c2+4];
        float2 jA  = HjA[c2], jB  = HjB[c2];
        float2 jA2 = HjA[c2+4], jB2 = HjB[c2+4];
        __half2 a0h = __floats2half2_rn(hiA.x*jA.x,  hiA.y*jA.y);
        __half2 a1h = __floats2half2_rn(hiA.x*jB.x,  hiA.y*jB.y);
        __half2 a2h = __floats2half2_rn(hiB.x*jA2.x, hiB.y*jA2.y);
        __half2 a3h = __floats2half2_rn(hiB.x*jB2.x, hiB.y*jB2.y);
        u32 a0 = *(u32*)&a0h, a1 = *(u32*)&a1h, a2 = *(u32*)&a2h, a3 = *(u32*)&a3h;
        #pragma unroll
        for (int nt = 0; nt < 8; nt++){
          asm volatile(
            "mma.sync.aligned.m16n8k16.row.col.f32.f16.f16.f32 "
            "{%0,%1,%2,%3},{%4,%5,%6,%7},{%8,%9},{%0,%1,%2,%3};"
            : "+f"(acc[nt][0]), "+f"(acc[nt][1]),
              "+f"(acc[nt][2]), "+f"(acc[nt][3])
            : "r"(a0),"r"(a1),"r"(a2),"r"(a3), "r"(b[2*nt]),"r"(b[2*nt+1]));
        }
      }

      // epilogue mh: lrelu + bias, column-planar store; invalid diag slots get 0
      #pragma unroll
      for (int nt = 0; nt < 8; nt++){
        float2 bb = *(const float2*)&b5s[ng*64 + nt*8 + qlane*2];
        int c2 = ng*32 + nt*4 + qlane;
        u32* colp = g_Tc + (size_t)c2*ES + tbase;
        #pragma unroll
        for (int h = 0; h < 2; h++){
          float tv0 = lrelu(acc[nt][2*h]   + bb.x);
          float tv1 = lrelu(acc[nt][2*h+1] + bb.y);
          int jj = mh*16 + qid + h*8;
          __half2 hv = __floats2half2_rn(tv0, tv1);
          u32 word = (offdiag || jj > ii) ? *(u32*)&hv : 0u;
          colp[jj] = word;
        }
      }
    }
  }
}

// ---------------- stats over column-planar t-cache (invalid slots are 0) ----------------
__global__ void __launch_bounds__(256)
k_stats(){
  __shared__ float rs[4*8];
  int blk = blockIdx.x;                 // 256 blocks
  int c2 = blk >> 2, quad = blk & 3;
  const uint4* ptr = (const uint4*)(g_Tc + (size_t)c2*ES + (size_t)quad*(ES/4));
  const int n4 = (int)(ES/4/4);         // 133120
  int tid = threadIdx.x;
  float s0=0.f, q0=0.f, s1=0.f, q1=0.f;
  for (int i = tid; i < n4; i += 256){
    uint4 v = ptr[i];
    float2 f0 = __half22float2(*(__half2*)&v.x);
    float2 f1 = __half22float2(*(__half2*)&v.y);
    float2 f2 = __half22float2(*(__half2*)&v.z);
    float2 f3 = __half22float2(*(__half2*)&v.w);
    s0 += (f0.x + f1.x) + (f2.x + f3.x);
    s1 += (f0.y + f1.y) + (f2.y + f3.y);
    q0 += (f0.x*f0.x + f1.x*f1.x) + (f2.x*f2.x + f3.x*f3.x);
    q1 += (f0.y*f0.y + f1.y*f1.y) + (f2.y*f2.y + f3.y*f3.y);
  }
  #pragma unroll
  for (int off = 16; off >= 1; off >>= 1){
    s0 += __shfl_xor_sync(0xffffffffu, s0, off);
    s1 += __shfl_xor_sync(0xffffffffu, s1, off);
    q0 += __shfl_xor_sync(0xffffffffu, q0, off);
    q1 += __shfl_xor_sync(0xffffffffu, q1, off);
  }
  int wid = tid >> 5;
  if ((tid & 31) == 0){
    rs[wid] = s0; rs[8 + wid] = s1; rs[16 + wid] = q0; rs[24 + wid] = q1;
  }
  __syncthreads();
  if (tid == 0){
    float a0=0.f, a1=0.f, b0=0.f, b1=0.f;
    #pragma unroll
    for (int w = 0; w < 8; w++){ a0+=rs[w]; a1+=rs[8+w]; b0+=rs[16+w]; b1+=rs[24+w]; }
    atomicAdd(&g_s5[2*c2],   a0);
    atomicAdd(&g_s5[2*c2+1], a1);
    atomicAdd(&g_q5[2*c2],   b0);
    atomicAdd(&g_q5[2*c2+1], b1);
  }
}

// ---------------- edge pass 2: column reads, in-block BN5 fold, coalesced writes ----------------
__global__ void __launch_bounds__(256)
k_edge2h(const float* __restrict__ W6, const float* __restrict__ b6,
         const float* __restrict__ g5, const float* __restrict__ be5,
         float* __restrict__ out){
  __shared__ float w0s[HH], w1s[HH], bts[HH], scal[2];
  __shared__ float2 prs[32*33];
  int tid = threadIdx.x;
  if (tid < HH){
    float m = g_s5[tid]/EDGEF;
    float v = g_q5[tid]/EDGEF - m*m;
    float a = rsqrtf(v + 1e-5f) * g5[tid];
    bts[tid] = be5[tid] - m*a;
    w0s[tid] = a*W6[tid*2];
    w1s[tid] = a*W6[tid*2 + 1];
  }
  __syncthreads();
  if (tid < 32){
    float t0 = 0.f, t1 = 0.f;
    for (int k = tid; k < HH; k += 32){
      t0 += bts[k]*W6[k*2];
      t1 += bts[k]*W6[k*2 + 1];
    }
    #pragma unroll
    for (int off = 16; off >= 1; off >>= 1){
      t0 += __shfl_xor_sync(0xffffffffu, t0, off);
      t1 += __shfl_xor_sync(0xffffffffu, t1, off);
    }
    if (tid == 0){ scal[0] = b6[0] + t0; scal[1] = b6[1] + t1; }
  }
  int p = blockIdx.x;
  int bi = 0, rem = p;
  while (rem >= NB - bi){ rem -= NB - bi; bi++; }
  int bj = bi + rem;
  __syncthreads();
  float b60 = scal[0], b61 = scal[1];

  #pragma unroll
  for (int s4 = 0; s4 < 4; s4++){
    int slot = s4*256 + tid;
    size_t base = (size_t)p*1024 + slot;
    float l0 = b60, l1 = b61;
    #pragma unroll 8
    for (int c2 = 0; c2 < 64; c2++){
      u32 v = g_Tc[(size_t)c2*ES + base];
      float2 f = __half22float2(*(__half2*)&v);
      l0 += f.x*w0s[2*c2] + f.y*w0s[2*c2+1];
      l1 += f.x*w1s[2*c2] + f.y*w1s[2*c2+1];
    }
    float q = __expf(l1 - l0);
    float inv = 1.f/(1.f + q);
    int ii = slot >> 5, jj = slot & 31;
    prs[ii*33 + jj] = make_float2(inv, q*inv);
  }
  __syncthreads();

  float2* o2 = (float2*)out;
  size_t rowi = (size_t)(bi*TI)*NN + bj*TI;
  size_t rowj = (size_t)(bj*TI)*NN + bi*TI;
  if (bi != bj){
    #pragma unroll
    for (int s4 = 0; s4 < 4; s4++){
      int idx = s4*256 + tid;
      int ii = idx >> 5, jj = idx & 31;
      o2[rowi + (size_t)ii*NN + jj] = prs[ii*33 + jj];
    }
    #pragma unroll
    for (int s4 = 0; s4 < 4; s4++){
      int idx = s4*256 + tid;
      int jj = idx >> 5, ii = idx & 31;
      o2[rowj + (size_t)jj*NN + ii] = prs[ii*33 + jj];
    }
  } else {
    #pragma unroll
    for (int s4 = 0; s4 < 4; s4++){
      int idx = s4*256 + tid;
      int ii = idx >> 5, jj = idx & 31;
      if (jj > ii) o2[rowi + (size_t)ii*NN + jj] = prs[ii*33 + jj];
    }
    #pragma unroll
    for (int s4 = 0; s4 < 4; s4++){
      int idx = s4*256 + tid;
      int jj = idx >> 5, ii = idx & 31;
      if (jj > ii) o2[rowj + (size_t)jj*NN + ii] = prs[ii*33 + jj];
    }
    if (tid < 32) o2[rowi + (size_t)tid*NN + tid] = make_float2(0.f, 0.f);
  }
}

// ---------------- launch ----------------
extern "C" void kernel_launch(void* const* d_in, const int* in_sizes, int n_in,
                              void* d_out, int out_size){
  const float* nf  = (const float*)d_in[1];
  const float* W1  = (const float*)d_in[2];
  const float* b1  = (const float*)d_in[3];
  const float* g1  = (const float*)d_in[4];
  const float* be1 = (const float*)d_in[5];
  const float* W2  = (const float*)d_in[6];
  const float* b2  = (const float*)d_in[7];
  const float* g2  = (const float*)d_in[8];
  const float* be2 = (const float*)d_in[9];
  const float* W3  = (const float*)d_in[10];
  const float* b3  = (const float*)d_in[11];
  const float* W5  = (const float*)d_in[12];
  const float* b5  = (const float*)d_in[13];
  const float* g5  = (const float*)d_in[14];
  const float* be5 = (const float*)d_in[15];
  const float* W6  = (const float*)d_in[16];
  const float* b6  = (const float*)d_in[17];
  float* out = (float*)d_out;

  const int N2_SMEM = (HH*HH + 8*HH) * 4;
  cudaFuncSetAttribute(k_node2, cudaFuncAttributeMaxDynamicSharedMemorySize, N2_SMEM);
  cudaFuncSetAttribute(k_edgeG, cudaFuncAttributeMaxDynamicSharedMemorySize, EDGE1_SMEM);

  k_init<<<1, 128>>>();
  k_node1<<<256, 128>>>(nf, W1, b1);
  k_fold1<<<1, 128>>>(W2, b2, g1, be1);
  k_node2<<<256, 128, N2_SMEM>>>();
  k_fold2<<<1, 128>>>(W3, b3, g2, be2);
  k_node3<<<256, 128>>>(nf);
  k_edgeG<<<NPAIR, 256, EDGE1_SMEM>>>(W5, b5);
  k_stats<<<256, 256>>>();
  k_edge2h<<<NPAIR, 256>>>(W6, b6, g5, be5, out);
}

// round 16
// speedup vs baseline: 1.4560x; 1.4560x over previous
#include <cuda_runtime.h>
#include <cuda_fp16.h>
#include <cstdint>

#define NN 2048
#define FF 64
#define HH 128
#define TI 32
#define NB (NN/TI)            // 64
#define NPAIR (NB*(NB+1)/2)   // 2080
#define EDGEF 2096128.0f      // NN*(NN-1)/2
#define ES ((size_t)NPAIR*1024)

typedef unsigned int u32;

// ---------------- scratch ----------------
__device__ float g_A1[NN*HH];
__device__ float g_A2[NN*HH];
__device__ float g_H3[NN*FF];
__device__ float g_W2f[HH*HH];
__device__ float g_b2f[HH];
__device__ float g_W3f[HH*FF];
__device__ float g_b3f[FF];
__device__ double g_s1[HH], g_q1[HH], g_s2[HH], g_q2[HH];
__device__ float g_s5[HH], g_q5[HH];
// t-cache, column-planar: g_Tc[c2*ES + slot], half2 per u32; invalid diag slots = 0
__device__ u32 g_Tc[64*ES];

__device__ __forceinline__ float lrelu(float x){ return fmaxf(x, 0.01f*x); }

// ---------------- init ----------------
__global__ void k_init(){
  int tid = threadIdx.x;
  if (tid < HH){
    g_s1[tid]=0.0; g_q1[tid]=0.0;
    g_s2[tid]=0.0; g_q2[tid]=0.0;
    g_s5[tid]=0.f; g_q5[tid]=0.f;
  }
}

// ---------------- node layer 1 ----------------
__global__ void k_node1(const float* __restrict__ nf, const float* __restrict__ W1,
                        const float* __restrict__ b1){
  __shared__ float nfs[8*FF];
  int tid = threadIdx.x;
  int r0  = blockIdx.x*8;
  for (int i = tid; i < 8*FF; i += 128) nfs[i] = nf[r0*FF + i];
  float w[FF];
  #pragma unroll
  for (int k = 0; k < FF; k++) w[k] = W1[k*HH + tid];
  float bc = b1[tid];
  __syncthreads();
  float s = 0.f, q = 0.f;
  #pragma unroll
  for (int r = 0; r < 8; r++){
    float a0=0.f, a1=0.f, a2=0.f, a3=0.f;
    #pragma unroll
    for (int k = 0; k < FF; k += 4){
      a0 += nfs[r*FF+k]*w[k];
      a1 += nfs[r*FF+k+1]*w[k+1];
      a2 += nfs[r*FF+k+2]*w[k+2];
      a3 += nfs[r*FF+k+3]*w[k+3];
    }
    float a = lrelu(bc + (a0+a1) + (a2+a3));
    g_A1[(r0+r)*HH + tid] = a;
    s += a; q += a*a;
  }
  atomicAdd(&g_s1[tid], (double)s);
  atomicAdd(&g_q1[tid], (double)q);
}

__global__ void k_fold1(const float* __restrict__ W2, const float* __restrict__ b2,
                        const float* __restrict__ g1, const float* __restrict__ be1){
  __shared__ float al[HH], bt[HH];
  int tid = threadIdx.x;
  double m = g_s1[tid]/(double)NN;
  double v = g_q1[tid]/(double)NN - m*m;
  float a = rsqrtf((float)v + 1e-5f) * g1[tid];
  al[tid] = a; bt[tid] = be1[tid] - (float)m*a;
  __syncthreads();
  float bb = b2[tid];
  for (int k = 0; k < HH; k++){
    float w = W2[k*HH + tid];
    g_W2f[k*HH + tid] = al[k]*w;
    bb += bt[k]*w;
  }
  g_b2f[tid] = bb;
}

// ---------------- node layer 2 ----------------
__global__ void k_node2(){
  extern __shared__ float sm2[];
  float* w2s = sm2;                 // 16384
  float* a1s = sm2 + HH*HH;         // 1024
  int tid = threadIdx.x;
  int r0  = blockIdx.x*8;
  for (int i = tid; i < HH*HH; i += 128) w2s[i] = g_W2f[i];
  for (int i = tid; i < 8*HH; i += 128) a1s[i] = g_A1[r0*HH + i];
  float bc = g_b2f[tid];
  __syncthreads();
  float acc[8];
  #pragma unroll
  for (int r = 0; r < 8; r++) acc[r] = 0.f;
  for (int kb = 0; kb < HH; kb += 8){
    float w0 = w2s[(kb+0)*HH+tid], w1 = w2s[(kb+1)*HH+tid];
    float w2 = w2s[(kb+2)*HH+tid], w3 = w2s[(kb+3)*HH+tid];
    float w4 = w2s[(kb+4)*HH+tid], w5 = w2s[(kb+5)*HH+tid];
    float w6 = w2s[(kb+6)*HH+tid], w7 = w2s[(kb+7)*HH+tid];
    #pragma unroll
    for (int r = 0; r < 8; r++){
      const float* ar = a1s + r*HH + kb;
      float p0 = ar[0]*w0 + ar[1]*w1;
      float p1 = ar[2]*w2 + ar[3]*w3;
      float p2 = ar[4]*w4 + ar[5]*w5;
      float p3 = ar[6]*w6 + ar[7]*w7;
      acc[r] += (p0+p1) + (p2+p3);
    }
  }
  float s = 0.f, q = 0.f;
  #pragma unroll
  for (int r = 0; r < 8; r++){
    float a = lrelu(acc[r] + bc);
    g_A2[(r0+r)*HH + tid] = a;
    s += a; q += a*a;
  }
  atomicAdd(&g_s2[tid], (double)s);
  atomicAdd(&g_q2[tid], (double)q);
}

__global__ void k_fold2(const float* __restrict__ W3, const float* __restrict__ b3,
                        const float* __restrict__ g2, const float* __restrict__ be2){
  __shared__ float al[HH], bt[HH];
  int tid = threadIdx.x;
  double m = g_s2[tid]/(double)NN;
  double v = g_q2[tid]/(double)NN - m*m;
  float a = rsqrtf((float)v + 1e-5f) * g2[tid];
  al[tid] = a; bt[tid] = be2[tid] - (float)m*a;
  __syncthreads();
  if (tid < FF){
    float bb = b3[tid];
    for (int k = 0; k < HH; k++){
      float w = W3[k*FF + tid];
      g_W3f[k*FF + tid] = al[k]*w;
      bb += bt[k]*w;
    }
    g_b3f[tid] = bb;
  }
}

// ---------------- node layer 3 ----------------
__global__ void k_node3(const float* __restrict__ nf){
  __shared__ float a2s[8*HH];     // 4KB
  __shared__ float w3s[HH*FF];    // 32KB
  int tid = threadIdx.x;
  int r0  = blockIdx.x*8;
  for (int i = tid; i < 8*HH; i += 128) a2s[i] = g_A2[r0*HH + i];
  for (int i = tid; i < HH*FF; i += 128) w3s[i] = g_W3f[i];
  __syncthreads();
  int c = tid & 63, rh = tid >> 6;
  float acc[4];
  #pragma unroll
  for (int r = 0; r < 4; r++) acc[r] = 0.f;
  for (int kb = 0; kb < HH; kb += 8){
    float w0 = w3s[(kb+0)*FF+c], w1 = w3s[(kb+1)*FF+c];
    float w2 = w3s[(kb+2)*FF+c], w3 = w3s[(kb+3)*FF+c];
    float w4 = w3s[(kb+4)*FF+c], w5 = w3s[(kb+5)*FF+c];
    float w6 = w3s[(kb+6)*FF+c], w7 = w3s[(kb+7)*FF+c];
    #pragma unroll
    for (int r = 0; r < 4; r++){
      const float* ar = a2s + (rh*4+r)*HH + kb;
      float p0 = ar[0]*w0 + ar[1]*w1;
      float p1 = ar[2]*w2 + ar[3]*w3;
      float p2 = ar[4]*w4 + ar[5]*w5;
      float p3 = ar[6]*w6 + ar[7]*w7;
      acc[r] += (p0+p1) + (p2+p3);
    }
  }
  #pragma unroll
  for (int r = 0; r < 4; r++){
    int rr = rh*4 + r;
    g_H3[(r0+rr)*FF + c] = acc[r] + g_b3f[c] + nf[(r0+rr)*FF + c];
  }
}

// ---------------- edge pass 1: fp16 mma, fp16 Hi/Hj (quad-interleaved), no stats ----------------
// SMEM floats: W5f 5120 | Hiq 1152 (32x72 halves) | Hjq 1152 | b5s 128 = 7552 floats
#define HQ_STR 36     // row stride in u32 (72 halves, 144B) — perfect 2-phase LDS.64
#define OFF_W5F 0
#define OFF_HIQ 5120
#define OFF_HJQ (OFF_HIQ+1152)
#define OFF_B5  (OFF_HJQ+1152)
#define EDGE1_SMEM ((OFF_B5 + 128)*4)   // 30720 bytes

__global__ void __launch_bounds__(256, 2)
k_edgeG(const float* __restrict__ W5, const float* __restrict__ b5){
  extern __shared__ float sm[];
  u32* w5f = (u32*)(sm + OFF_W5F);      // fragment-order B, lane stride 20 u32
  u32* Hiq = (u32*)(sm + OFF_HIQ);      // quad-interleaved half pairs
  u32* Hjq = (u32*)(sm + OFF_HJQ);
  float* b5s = sm + OFF_B5;

  int tid = threadIdx.x;
  int lane = tid & 31, wid = tid >> 5;
  int mg = wid & 3, ng = wid >> 2;
  int qid = lane >> 2, qlane = lane & 3;

  int p = blockIdx.x, bi = 0, rem = p;
  while (rem >= NB - bi){ rem -= NB - bi; bi++; }
  int bj = bi + rem;

  // B fragments (as R12): b = half2(W5[k][n], W5[k+1][n])
  for (int idx = tid; idx < 4096; idx += 256){
    int g  = idx >> 11;
    int ks = (idx >> 9) & 3;
    int ln = (idx >> 4) & 31;
    int f  = idx & 15;
    int qi = ln >> 2, ql = ln & 3;
    int nt = f >> 1, w = f & 1;
    int k = ks*16 + ql*2 + w*8;
    int n = g*64 + nt*8 + qi;
    __half2 hv = __floats2half2_rn(W5[k*HH + n], W5[(k+1)*HH + n]);
    w5f[((g*4 + ks)*32 + ln)*20 + f] = *(u32*)&hv;
  }
  // Hi/Hj as half2 pairs: u32 at [r*36 + ks*8 + ql*2 + w] = half2(H[k], H[k+1]),
  // k = ks*16 + ql*2 + w*8
  for (int i = tid; i < TI*32; i += 256){
    int r = i >> 5, f = i & 31;           // f = u32 index within row (32 used of 36)
    int ks = f >> 3, ql = (f >> 1) & 3, w = f & 1;
    int k = ks*16 + ql*2 + w*8;
    const float* hi = &g_H3[(bi*TI + r)*FF + k];
    const float* hj = &g_H3[(bj*TI + r)*FF + k];
    __half2 hvi = __floats2half2_rn(hi[0], hi[1]);
    __half2 hvj = __floats2half2_rn(hj[0], hj[1]);
    Hiq[r*HQ_STR + f] = *(u32*)&hvi;
    Hjq[r*HQ_STR + f] = *(u32*)&hvj;
  }
  if (tid < HH) b5s[tid] = b5[tid];
  __syncthreads();
  // ---- mainloop: NO barriers below (all smem read-only) ----

  size_t pbase = (size_t)p*1024;
  bool offdiag = (bi != bj);

  for (int t = 0; t < 8; t++){
    float acc[2][8][4];
    #pragma unroll
    for (int mt = 0; mt < 2; mt++)
      #pragma unroll
      for (int nt = 0; nt < 8; nt++)
        #pragma unroll
        for (int c = 0; c < 4; c++) acc[mt][nt][c] = 0.f;

    int ii = t*4 + mg;
    const u32* HiR = Hiq + ii*HQ_STR;

    #pragma unroll
    for (int ks = 0; ks < 4; ks++){
      const uint4* Bp = (const uint4*)(w5f + ((ng*4 + ks)*32 + lane)*20);
      uint4 B0 = Bp[0], B1 = Bp[1], B2 = Bp[2], B3 = Bp[3];
      u32 b[16] = {B0.x,B0.y,B0.z,B0.w, B1.x,B1.y,B1.z,B1.w,
                   B2.x,B2.y,B2.z,B2.w, B3.x,B3.y,B3.z,B3.w};
      uint2 hi = *(const uint2*)(HiR + ks*8 + qlane*2);
      __half2 hi0 = *(__half2*)&hi.x, hi1 = *(__half2*)&hi.y;
      #pragma unroll
      for (int mt = 0; mt < 2; mt++){
        const u32* HjA = Hjq + (mt*16 + qid)*HQ_STR + ks*8 + qlane*2;
        uint2 jA = *(const uint2*)HjA;
        uint2 jB = *(const uint2*)(HjA + 8*HQ_STR);
        __half2 a0h = __hmul2(hi0, *(__half2*)&jA.x);
        __half2 a1h = __hmul2(hi0, *(__half2*)&jB.x);
        __half2 a2h = __hmul2(hi1, *(__half2*)&jA.y);
        __half2 a3h = __hmul2(hi1, *(__half2*)&jB.y);
        u32 a0 = *(u32*)&a0h, a1 = *(u32*)&a1h, a2 = *(u32*)&a2h, a3 = *(u32*)&a3h;
        #pragma unroll
        for (int nt = 0; nt < 8; nt++){
          asm volatile(
            "mma.sync.aligned.m16n8k16.row.col.f32.f16.f16.f32 "
            "{%0,%1,%2,%3},{%4,%5,%6,%7},{%8,%9},{%0,%1,%2,%3};"
            : "+f"(acc[mt][nt][0]), "+f"(acc[mt][nt][1]),
              "+f"(acc[mt][nt][2]), "+f"(acc[mt][nt][3])
            : "r"(a0),"r"(a1),"r"(a2),"r"(a3), "r"(b[2*nt]),"r"(b[2*nt+1]));
        }
      }
    }

    // epilogue: lrelu + bias, column-planar store; invalid diagonal slots get 0
    size_t tbase = pbase + (size_t)t*128 + mg*32;
    #pragma unroll
    for (int nt = 0; nt < 8; nt++){
      float2 bb = *(const float2*)&b5s[ng*64 + nt*8 + qlane*2];
      int c2 = ng*32 + nt*4 + qlane;
      u32* colp = g_Tc + (size_t)c2*ES + tbase;
      #pragma unroll
      for (int mt = 0; mt < 2; mt++)
        #pragma unroll
        for (int h = 0; h < 2; h++){
          float tv0 = lrelu(acc[mt][nt][2*h]   + bb.x);
          float tv1 = lrelu(acc[mt][nt][2*h+1] + bb.y);
          int jj = mt*16 + qid + h*8;
          __half2 hv = __floats2half2_rn(tv0, tv1);
          u32 word = (offdiag || jj > ii) ? *(u32*)&hv : 0u;
          colp[jj] = word;
        }
    }
  }
}

// ---------------- stats over column-planar t-cache (invalid slots are 0) ----------------
__global__ void __launch_bounds__(256)
k_stats(){
  __shared__ float rs[4*8];
  int blk = blockIdx.x;                 // 256 blocks
  int c2 = blk >> 2, quad = blk & 3;
  const uint4* ptr = (const uint4*)(g_Tc + (size_t)c2*ES + (size_t)quad*(ES/4));
  const int n4 = (int)(ES/4/4);         // 133120
  int tid = threadIdx.x;
  float s0=0.f, q0=0.f, s1=0.f, q1=0.f;
  for (int i = tid; i < n4; i += 256){
    uint4 v = ptr[i];
    float2 f0 = __half22float2(*(__half2*)&v.x);
    float2 f1 = __half22float2(*(__half2*)&v.y);
    float2 f2 = __half22float2(*(__half2*)&v.z);
    float2 f3 = __half22float2(*(__half2*)&v.w);
    s0 += (f0.x + f1.x) + (f2.x + f3.x);
    s1 += (f0.y + f1.y) + (f2.y + f3.y);
    q0 += (f0.x*f0.x + f1.x*f1.x) + (f2.x*f2.x + f3.x*f3.x);
    q1 += (f0.y*f0.y + f1.y*f1.y) + (f2.y*f2.y + f3.y*f3.y);
  }
  #pragma unroll
  for (int off = 16; off >= 1; off >>= 1){
    s0 += __shfl_xor_sync(0xffffffffu, s0, off);
    s1 += __shfl_xor_sync(0xffffffffu, s1, off);
    q0 += __shfl_xor_sync(0xffffffffu, q0, off);
    q1 += __shfl_xor_sync(0xffffffffu, q1, off);
  }
  int wid = tid >> 5;
  if ((tid & 31) == 0){
    rs[wid] = s0; rs[8 + wid] = s1; rs[16 + wid] = q0; rs[24 + wid] = q1;
  }
  __syncthreads();
  if (tid == 0){
    float a0=0.f, a1=0.f, b0=0.f, b1=0.f;
    #pragma unroll
    for (int w = 0; w < 8; w++){ a0+=rs[w]; a1+=rs[8+w]; b0+=rs[16+w]; b1+=rs[24+w]; }
    atomicAdd(&g_s5[2*c2],   a0);
    atomicAdd(&g_s5[2*c2+1], a1);
    atomicAdd(&g_q5[2*c2],   b0);
    atomicAdd(&g_q5[2*c2+1], b1);
  }
}

// ---------------- edge pass 2: column reads, in-block BN5 fold, coalesced writes ----------------
__global__ void __launch_bounds__(256)
k_edge2h(const float* __restrict__ W6, const float* __restrict__ b6,
         const float* __restrict__ g5, const float* __restrict__ be5,
         float* __restrict__ out){
  __shared__ float w0s[HH], w1s[HH], bts[HH], scal[2];
  __shared__ float2 prs[32*33];
  int tid = threadIdx.x;
  if (tid < HH){
    float m = g_s5[tid]/EDGEF;
    float v = g_q5[tid]/EDGEF - m*m;
    float a = rsqrtf(v + 1e-5f) * g5[tid];
    bts[tid] = be5[tid] - m*a;
    w0s[tid] = a*W6[tid*2];
    w1s[tid] = a*W6[tid*2 + 1];
  }
  __syncthreads();
  if (tid < 32){
    float t0 = 0.f, t1 = 0.f;
    for (int k = tid; k < HH; k += 32){
      t0 += bts[k]*W6[k*2];
      t1 += bts[k]*W6[k*2 + 1];
    }
    #pragma unroll
    for (int off = 16; off >= 1; off >>= 1){
      t0 += __shfl_xor_sync(0xffffffffu, t0, off);
      t1 += __shfl_xor_sync(0xffffffffu, t1, off);
    }
    if (tid == 0){ scal[0] = b6[0] + t0; scal[1] = b6[1] + t1; }
  }
  int p = blockIdx.x;
  int bi = 0, rem = p;
  while (rem >= NB - bi){ rem -= NB - bi; bi++; }
  int bj = bi + rem;
  __syncthreads();
  float b60 = scal[0], b61 = scal[1];

  #pragma unroll
  for (int s4 = 0; s4 < 4; s4++){
    int slot = s4*256 + tid;
    size_t base = (size_t)p*1024 + slot;
    float l0 = b60, l1 = b61;
    #pragma unroll 8
    for (int c2 = 0; c2 < 64; c2++){
      u32 v = g_Tc[(size_t)c2*ES + base];
      float2 f = __half22float2(*(__half2*)&v);
      l0 += f.x*w0s[2*c2] + f.y*w0s[2*c2+1];
      l1 += f.x*w1s[2*c2] + f.y*w1s[2*c2+1];
    }
    float q = __expf(l1 - l0);
    float inv = 1.f/(1.f + q);
    int ii = slot >> 5, jj = slot & 31;
    prs[ii*33 + jj] = make_float2(inv, q*inv);
  }
  __syncthreads();

  float2* o2 = (float2*)out;
  size_t rowi = (size_t)(bi*TI)*NN + bj*TI;
  size_t rowj = (size_t)(bj*TI)*NN + bi*TI;
  if (bi != bj){
    #pragma unroll
    for (int s4 = 0; s4 < 4; s4++){
      int idx = s4*256 + tid;
      int ii = idx >> 5, jj = idx & 31;
      o2[rowi + (size_t)ii*NN + jj] = prs[ii*33 + jj];
    }
    #pragma unroll
    for (int s4 = 0; s4 < 4; s4++){
      int idx = s4*256 + tid;
      int jj = idx >> 5, ii = idx & 31;
      o2[rowj + (size_t)jj*NN + ii] = prs[ii*33 + jj];
    }
  } else {
    #pragma unroll
    for (int s4 = 0; s4 < 4; s4++){
      int idx = s4*256 + tid;
      int ii = idx >> 5, jj = idx & 31;
      if (jj > ii) o2[rowi + (size_t)ii*NN + jj] = prs[ii*33 + jj];
    }
    #pragma unroll
    for (int s4 = 0; s4 < 4; s4++){
      int idx = s4*256 + tid;
      int jj = idx >> 5, ii = idx & 31;
      if (jj > ii) o2[rowj + (size_t)jj*NN + ii] = prs[ii*33 + jj];
    }
    if (tid < 32) o2[rowi + (size_t)tid*NN + tid] = make_float2(0.f, 0.f);
  }
}

// ---------------- launch ----------------
extern "C" void kernel_launch(void* const* d_in, const int* in_sizes, int n_in,
                              void* d_out, int out_size){
  const float* nf  = (const float*)d_in[1];
  const float* W1  = (const float*)d_in[2];
  const float* b1  = (const float*)d_in[3];
  const float* g1  = (const float*)d_in[4];
  const float* be1 = (const float*)d_in[5];
  const float* W2  = (const float*)d_in[6];
  const float* b2  = (const float*)d_in[7];
  const float* g2  = (const float*)d_in[8];
  const float* be2 = (const float*)d_in[9];
  const float* W3  = (const float*)d_in[10];
  const float* b3  = (const float*)d_in[11];
  const float* W5  = (const float*)d_in[12];
  const float* b5  = (const float*)d_in[13];
  const float* g5  = (const float*)d_in[14];
  const float* be5 = (const float*)d_in[15];
  const float* W6  = (const float*)d_in[16];
  const float* b6  = (const float*)d_in[17];
  float* out = (float*)d_out;

  const int N2_SMEM = (HH*HH + 8*HH) * 4;
  cudaFuncSetAttribute(k_node2, cudaFuncAttributeMaxDynamicSharedMemorySize, N2_SMEM);
  cudaFuncSetAttribute(k_edgeG, cudaFuncAttributeMaxDynamicSharedMemorySize, EDGE1_SMEM);

  k_init<<<1, 128>>>();
  k_node1<<<256, 128>>>(nf, W1, b1);
  k_fold1<<<1, 128>>>(W2, b2, g1, be1);
  k_node2<<<256, 128, N2_SMEM>>>();
  k_fold2<<<1, 128>>>(W3, b3, g2, be2);
  k_node3<<<256, 128>>>(nf);
  k_edgeG<<<NPAIR, 256, EDGE1_SMEM>>>(W5, b5);
  k_stats<<<256, 256>>>();
  k_edge2h<<<NPAIR, 256>>>(W6, b6, g5, be5, out);
}

// round 17
// speedup vs baseline: 1.4879x; 1.0219x over previous
#include <cuda_runtime.h>
#include <cuda_fp16.h>
#include <cstdint>

#define NN 2048
#define FF 64
#define HH 128
#define TI 32
#define NB (NN/TI)            // 64
#define NPAIR (NB*(NB+1)/2)   // 2080
#define EDGEF 2096128.0f      // NN*(NN-1)/2
#define ES ((size_t)NPAIR*1024)

typedef unsigned int u32;

// ---------------- scratch ----------------
__device__ float g_A1[NN*HH];
__device__ float g_A2[NN*HH];
__device__ float g_H3[NN*FF];
__device__ float g_W2f[HH*HH];
__device__ float g_b2f[HH];
__device__ float g_W3f[HH*FF];
__device__ float g_b3f[FF];
__device__ double g_s1[HH], g_q1[HH], g_s2[HH], g_q2[HH];
__device__ float g_s5[HH], g_q5[HH];
// t-cache, column-planar: g_Tc[c2*ES + slot], half2 per u32; invalid diag slots = 0
__device__ u32 g_Tc[64*ES];

__device__ __forceinline__ float lrelu(float x){ return fmaxf(x, 0.01f*x); }

// ---------------- init ----------------
__global__ void k_init(){
  int tid = threadIdx.x;
  if (tid < HH){
    g_s1[tid]=0.0; g_q1[tid]=0.0;
    g_s2[tid]=0.0; g_q2[tid]=0.0;
    g_s5[tid]=0.f; g_q5[tid]=0.f;
  }
}

// ---------------- node layer 1 ----------------
__global__ void k_node1(const float* __restrict__ nf, const float* __restrict__ W1,
                        const float* __restrict__ b1){
  __shared__ float nfs[8*FF];
  int tid = threadIdx.x;
  int r0  = blockIdx.x*8;
  for (int i = tid; i < 8*FF; i += 128) nfs[i] = nf[r0*FF + i];
  float w[FF];
  #pragma unroll
  for (int k = 0; k < FF; k++) w[k] = W1[k*HH + tid];
  float bc = b1[tid];
  __syncthreads();
  float s = 0.f, q = 0.f;
  #pragma unroll
  for (int r = 0; r < 8; r++){
    float a0=0.f, a1=0.f, a2=0.f, a3=0.f;
    #pragma unroll
    for (int k = 0; k < FF; k += 4){
      a0 += nfs[r*FF+k]*w[k];
      a1 += nfs[r*FF+k+1]*w[k+1];
      a2 += nfs[r*FF+k+2]*w[k+2];
      a3 += nfs[r*FF+k+3]*w[k+3];
    }
    float a = lrelu(bc + (a0+a1) + (a2+a3));
    g_A1[(r0+r)*HH + tid] = a;
    s += a; q += a*a;
  }
  atomicAdd(&g_s1[tid], (double)s);
  atomicAdd(&g_q1[tid], (double)q);
}

__global__ void k_fold1(const float* __restrict__ W2, const float* __restrict__ b2,
                        const float* __restrict__ g1, const float* __restrict__ be1){
  __shared__ float al[HH], bt[HH];
  int tid = threadIdx.x;
  double m = g_s1[tid]/(double)NN;
  double v = g_q1[tid]/(double)NN - m*m;
  float a = rsqrtf((float)v + 1e-5f) * g1[tid];
  al[tid] = a; bt[tid] = be1[tid] - (float)m*a;
  __syncthreads();
  float bb = b2[tid];
  for (int k = 0; k < HH; k++){
    float w = W2[k*HH + tid];
    g_W2f[k*HH + tid] = al[k]*w;
    bb += bt[k]*w;
  }
  g_b2f[tid] = bb;
}

// ---------------- node layer 2 ----------------
__global__ void k_node2(){
  extern __shared__ float sm2[];
  float* w2s = sm2;                 // 16384
  float* a1s = sm2 + HH*HH;         // 1024
  int tid = threadIdx.x;
  int r0  = blockIdx.x*8;
  for (int i = tid; i < HH*HH; i += 128) w2s[i] = g_W2f[i];
  for (int i = tid; i < 8*HH; i += 128) a1s[i] = g_A1[r0*HH + i];
  float bc = g_b2f[tid];
  __syncthreads();
  float acc[8];
  #pragma unroll
  for (int r = 0; r < 8; r++) acc[r] = 0.f;
  for (int kb = 0; kb < HH; kb += 8){
    float w0 = w2s[(kb+0)*HH+tid], w1 = w2s[(kb+1)*HH+tid];
    float w2 = w2s[(kb+2)*HH+tid], w3 = w2s[(kb+3)*HH+tid];
    float w4 = w2s[(kb+4)*HH+tid], w5 = w2s[(kb+5)*HH+tid];
    float w6 = w2s[(kb+6)*HH+tid], w7 = w2s[(kb+7)*HH+tid];
    #pragma unroll
    for (int r = 0; r < 8; r++){
      const float* ar = a1s + r*HH + kb;
      float p0 = ar[0]*w0 + ar[1]*w1;
      float p1 = ar[2]*w2 + ar[3]*w3;
      float p2 = ar[4]*w4 + ar[5]*w5;
      float p3 = ar[6]*w6 + ar[7]*w7;
      acc[r] += (p0+p1) + (p2+p3);
    }
  }
  float s = 0.f, q = 0.f;
  #pragma unroll
  for (int r = 0; r < 8; r++){
    float a = lrelu(acc[r] + bc);
    g_A2[(r0+r)*HH + tid] = a;
    s += a; q += a*a;
  }
  atomicAdd(&g_s2[tid], (double)s);
  atomicAdd(&g_q2[tid], (double)q);
}

__global__ void k_fold2(const float* __restrict__ W3, const float* __restrict__ b3,
                        const float* __restrict__ g2, const float* __restrict__ be2){
  __shared__ float al[HH], bt[HH];
  int tid = threadIdx.x;
  double m = g_s2[tid]/(double)NN;
  double v = g_q2[tid]/(double)NN - m*m;
  float a = rsqrtf((float)v + 1e-5f) * g2[tid];
  al[tid] = a; bt[tid] = be2[tid] - (float)m*a;
  __syncthreads();
  if (tid < FF){
    float bb = b3[tid];
    for (int k = 0; k < HH; k++){
      float w = W3[k*FF + tid];
      g_W3f[k*FF + tid] = al[k]*w;
      bb += bt[k]*w;
    }
    g_b3f[tid] = bb;
  }
}

// ---------------- node layer 3 ----------------
__global__ void k_node3(const float* __restrict__ nf){
  __shared__ float a2s[8*HH];     // 4KB
  __shared__ float w3s[HH*FF];    // 32KB
  int tid = threadIdx.x;
  int r0  = blockIdx.x*8;
  for (int i = tid; i < 8*HH; i += 128) a2s[i] = g_A2[r0*HH + i];
  for (int i = tid; i < HH*FF; i += 128) w3s[i] = g_W3f[i];
  __syncthreads();
  int c = tid & 63, rh = tid >> 6;
  float acc[4];
  #pragma unroll
  for (int r = 0; r < 4; r++) acc[r] = 0.f;
  for (int kb = 0; kb < HH; kb += 8){
    float w0 = w3s[(kb+0)*FF+c], w1 = w3s[(kb+1)*FF+c];
    float w2 = w3s[(kb+2)*FF+c], w3 = w3s[(kb+3)*FF+c];
    float w4 = w3s[(kb+4)*FF+c], w5 = w3s[(kb+5)*FF+c];
    float w6 = w3s[(kb+6)*FF+c], w7 = w3s[(kb+7)*FF+c];
    #pragma unroll
    for (int r = 0; r < 4; r++){
      const float* ar = a2s + (rh*4+r)*HH + kb;
      float p0 = ar[0]*w0 + ar[1]*w1;
      float p1 = ar[2]*w2 + ar[3]*w3;
      float p2 = ar[4]*w4 + ar[5]*w5;
      float p3 = ar[6]*w6 + ar[7]*w7;
      acc[r] += (p0+p1) + (p2+p3);
    }
  }
  #pragma unroll
  for (int r = 0; r < 4; r++){
    int rr = rh*4 + r;
    g_H3[(r0+rr)*FF + c] = acc[r] + g_b3f[c] + nf[(r0+rr)*FF + c];
  }
}

// ---------------- edge pass 1: fp16 mma, fp16 Hi/Hj (stride-40, conflict-free), no stats ----------------
// SMEM floats: W5f 5120 | Hiq 1280 (32x40 u32 /2) | Hjq 1280 | b5s 128
#define HQ_STR 40     // row stride in u32; 40 ≡ 8 (mod 32) -> conflict-free LDS.64
#define OFF_W5F 0
#define OFF_HIQ 5120
#define OFF_HJQ (OFF_HIQ+1280)
#define OFF_B5  (OFF_HJQ+1280)
#define EDGE1_SMEM ((OFF_B5 + 128)*4)   // 31232 bytes

__global__ void __launch_bounds__(256, 2)
k_edgeG(const float* __restrict__ W5, const float* __restrict__ b5){
  extern __shared__ float sm[];
  u32* w5f = (u32*)(sm + OFF_W5F);      // fragment-order B, lane stride 20 u32
  u32* Hiq = (u32*)(sm + OFF_HIQ);      // quad-interleaved half pairs
  u32* Hjq = (u32*)(sm + OFF_HJQ);
  float* b5s = sm + OFF_B5;

  int tid = threadIdx.x;
  int lane = tid & 31, wid = tid >> 5;
  int mg = wid & 3, ng = wid >> 2;
  int qid = lane >> 2, qlane = lane & 3;

  int p = blockIdx.x, bi = 0, rem = p;
  while (rem >= NB - bi){ rem -= NB - bi; bi++; }
  int bj = bi + rem;

  // B fragments: b = half2(W5[k][n], W5[k+1][n])
  for (int idx = tid; idx < 4096; idx += 256){
    int g  = idx >> 11;
    int ks = (idx >> 9) & 3;
    int ln = (idx >> 4) & 31;
    int f  = idx & 15;
    int qi = ln >> 2, ql = ln & 3;
    int nt = f >> 1, w = f & 1;
    int k = ks*16 + ql*2 + w*8;
    int n = g*64 + nt*8 + qi;
    __half2 hv = __floats2half2_rn(W5[k*HH + n], W5[(k+1)*HH + n]);
    w5f[((g*4 + ks)*32 + ln)*20 + f] = *(u32*)&hv;
  }
  // Hi/Hj as half2 pairs: u32 at [r*40 + ks*8 + ql*2 + w] = half2(H[k], H[k+1]),
  // k = ks*16 + ql*2 + w*8
  for (int i = tid; i < TI*32; i += 256){
    int r = i >> 5, f = i & 31;
    int ks = f >> 3, ql = (f >> 1) & 3, w = f & 1;
    int k = ks*16 + ql*2 + w*8;
    const float* hi = &g_H3[(bi*TI + r)*FF + k];
    const float* hj = &g_H3[(bj*TI + r)*FF + k];
    __half2 hvi = __floats2half2_rn(hi[0], hi[1]);
    __half2 hvj = __floats2half2_rn(hj[0], hj[1]);
    Hiq[r*HQ_STR + f] = *(u32*)&hvi;
    Hjq[r*HQ_STR + f] = *(u32*)&hvj;
  }
  if (tid < HH) b5s[tid] = b5[tid];
  __syncthreads();
  // ---- mainloop: NO barriers below (all smem read-only) ----

  size_t pbase = (size_t)p*1024;
  bool offdiag = (bi != bj);

  for (int t = 0; t < 8; t++){
    float acc[2][8][4];
    #pragma unroll
    for (int mt = 0; mt < 2; mt++)
      #pragma unroll
      for (int nt = 0; nt < 8; nt++)
        #pragma unroll
        for (int c = 0; c < 4; c++) acc[mt][nt][c] = 0.f;

    int ii = t*4 + mg;
    const u32* HiR = Hiq + ii*HQ_STR;

    #pragma unroll
    for (int ks = 0; ks < 4; ks++){
      const uint4* Bp = (const uint4*)(w5f + ((ng*4 + ks)*32 + lane)*20);
      uint4 B0 = Bp[0], B1 = Bp[1], B2 = Bp[2], B3 = Bp[3];
      u32 b[16] = {B0.x,B0.y,B0.z,B0.w, B1.x,B1.y,B1.z,B1.w,
                   B2.x,B2.y,B2.z,B2.w, B3.x,B3.y,B3.z,B3.w};
      uint2 hi = *(const uint2*)(HiR + ks*8 + qlane*2);
      __half2 hi0 = *(__half2*)&hi.x, hi1 = *(__half2*)&hi.y;
      #pragma unroll
      for (int mt = 0; mt < 2; mt++){
        const u32* HjA = Hjq + (mt*16 + qid)*HQ_STR + ks*8 + qlane*2;
        uint2 jA = *(const uint2*)HjA;
        uint2 jB = *(const uint2*)(HjA + 8*HQ_STR);
        __half2 a0h = __hmul2(hi0, *(__half2*)&jA.x);
        __half2 a1h = __hmul2(hi0, *(__half2*)&jB.x);
        __half2 a2h = __hmul2(hi1, *(__half2*)&jA.y);
        __half2 a3h = __hmul2(hi1, *(__half2*)&jB.y);
        u32 a0 = *(u32*)&a0h, a1 = *(u32*)&a1h, a2 = *(u32*)&a2h, a3 = *(u32*)&a3h;
        #pragma unroll
        for (int nt = 0; nt < 8; nt++){
          asm volatile(
            "mma.sync.aligned.m16n8k16.row.col.f32.f16.f16.f32 "
            "{%0,%1,%2,%3},{%4,%5,%6,%7},{%8,%9},{%0,%1,%2,%3};"
            : "+f"(acc[mt][nt][0]), "+f"(acc[mt][nt][1]),
              "+f"(acc[mt][nt][2]), "+f"(acc[mt][nt][3])
            : "r"(a0),"r"(a1),"r"(a2),"r"(a3), "r"(b[2*nt]),"r"(b[2*nt+1]));
        }
      }
    }

    // epilogue: lrelu + bias, column-planar store; invalid diagonal slots get 0
    size_t tbase = pbase + (size_t)t*128 + mg*32;
    #pragma unroll
    for (int nt = 0; nt < 8; nt++){
      float2 bb = *(const float2*)&b5s[ng*64 + nt*8 + qlane*2];
      int c2 = ng*32 + nt*4 + qlane;
      u32* colp = g_Tc + (size_t)c2*ES + tbase;
      #pragma unroll
      for (int mt = 0; mt < 2; mt++)
        #pragma unroll
        for (int h = 0; h < 2; h++){
          float tv0 = lrelu(acc[mt][nt][2*h]   + bb.x);
          float tv1 = lrelu(acc[mt][nt][2*h+1] + bb.y);
          int jj = mt*16 + qid + h*8;
          __half2 hv = __floats2half2_rn(tv0, tv1);
          u32 word = (offdiag || jj > ii) ? *(u32*)&hv : 0u;
          colp[jj] = word;
        }
    }
  }
}

// ---------------- stats over column-planar t-cache (invalid slots are 0) ----------------
__global__ void __launch_bounds__(256)
k_stats(){
  __shared__ float rs[4*8];
  int blk = blockIdx.x;                 // 256 blocks
  int c2 = blk >> 2, quad = blk & 3;
  const uint4* ptr = (const uint4*)(g_Tc + (size_t)c2*ES + (size_t)quad*(ES/4));
  const int n4 = (int)(ES/4/4);         // 133120
  int tid = threadIdx.x;
  float s0=0.f, q0=0.f, s1=0.f, q1=0.f;
  for (int i = tid; i < n4; i += 256){
    uint4 v = ptr[i];
    float2 f0 = __half22float2(*(__half2*)&v.x);
    float2 f1 = __half22float2(*(__half2*)&v.y);
    float2 f2 = __half22float2(*(__half2*)&v.z);
    float2 f3 = __half22float2(*(__half2*)&v.w);
    s0 += (f0.x + f1.x) + (f2.x + f3.x);
    s1 += (f0.y + f1.y) + (f2.y + f3.y);
    q0 += (f0.x*f0.x + f1.x*f1.x) + (f2.x*f2.x + f3.x*f3.x);
    q1 += (f0.y*f0.y + f1.y*f1.y) + (f2.y*f2.y + f3.y*f3.y);
  }
  #pragma unroll
  for (int off = 16; off >= 1; off >>= 1){
    s0 += __shfl_xor_sync(0xffffffffu, s0, off);
    s1 += __shfl_xor_sync(0xffffffffu, s1, off);
    q0 += __shfl_xor_sync(0xffffffffu, q0, off);
    q1 += __shfl_xor_sync(0xffffffffu, q1, off);
  }
  int wid = tid >> 5;
  if ((tid & 31) == 0){
    rs[wid] = s0; rs[8 + wid] = s1; rs[16 + wid] = q0; rs[24 + wid] = q1;
  }
  __syncthreads();
  if (tid == 0){
    float a0=0.f, a1=0.f, b0=0.f, b1=0.f;
    #pragma unroll
    for (int w = 0; w < 8; w++){ a0+=rs[w]; a1+=rs[8+w]; b0+=rs[16+w]; b1+=rs[24+w]; }
    atomicAdd(&g_s5[2*c2],   a0);
    atomicAdd(&g_s5[2*c2+1], a1);
    atomicAdd(&g_q5[2*c2],   b0);
    atomicAdd(&g_q5[2*c2+1], b1);
  }
}

// ---------------- edge pass 2: column reads, in-block BN5 fold, coalesced writes ----------------
__global__ void __launch_bounds__(256)
k_edge2h(const float* __restrict__ W6, const float* __restrict__ b6,
         const float* __restrict__ g5, const float* __restrict__ be5,
         float* __restrict__ out){
  __shared__ float w0s[HH], w1s[HH], bts[HH], scal[2];
  __shared__ float2 prs[32*33];
  int tid = threadIdx.x;
  if (tid < HH){
    float m = g_s5[tid]/EDGEF;
    float v = g_q5[tid]/EDGEF - m*m;
    float a = rsqrtf(v + 1e-5f) * g5[tid];
    bts[tid] = be5[tid] - m*a;
    w0s[tid] = a*W6[tid*2];
    w1s[tid] = a*W6[tid*2 + 1];
  }
  __syncthreads();
  if (tid < 32){
    float t0 = 0.f, t1 = 0.f;
    for (int k = tid; k < HH; k += 32){
      t0 += bts[k]*W6[k*2];
      t1 += bts[k]*W6[k*2 + 1];
    }
    #pragma unroll
    for (int off = 16; off >= 1; off >>= 1){
      t0 += __shfl_xor_sync(0xffffffffu, t0, off);
      t1 += __shfl_xor_sync(0xffffffffu, t1, off);
    }
    if (tid == 0){ scal[0] = b6[0] + t0; scal[1] = b6[1] + t1; }
  }
  int p = blockIdx.x;
  int bi = 0, rem = p;
  while (rem >= NB - bi){ rem -= NB - bi; bi++; }
  int bj = bi + rem;
  __syncthreads();
  float b60 = scal[0], b61 = scal[1];

  #pragma unroll
  for (int s4 = 0; s4 < 4; s4++){
    int slot = s4*256 + tid;
    size_t base = (size_t)p*1024 + slot;
    float l0 = b60, l1 = b61;
    #pragma unroll 8
    for (int c2 = 0; c2 < 64; c2++){
      u32 v = g_Tc[(size_t)c2*ES + base];
      float2 f = __half22float2(*(__half2*)&v);
      l0 += f.x*w0s[2*c2] + f.y*w0s[2*c2+1];
      l1 += f.x*w1s[2*c2] + f.y*w1s[2*c2+1];
    }
    float q = __expf(l1 - l0);
    float inv = 1.f/(1.f + q);
    int ii = slot >> 5, jj = slot & 31;
    prs[ii*33 + jj] = make_float2(inv, q*inv);
  }
  __syncthreads();

  float2* o2 = (float2*)out;
  size_t rowi = (size_t)(bi*TI)*NN + bj*TI;
  size_t rowj = (size_t)(bj*TI)*NN + bi*TI;
  if (bi != bj){
    #pragma unroll
    for (int s4 = 0; s4 < 4; s4++){
      int idx = s4*256 + tid;
      int ii = idx >> 5, jj = idx & 31;
      o2[rowi + (size_t)ii*NN + jj] = prs[ii*33 + jj];
    }
    #pragma unroll
    for (int s4 = 0; s4 < 4; s4++){
      int idx = s4*256 + tid;
      int jj = idx >> 5, ii = idx & 31;
      o2[rowj + (size_t)jj*NN + ii] = prs[ii*33 + jj];
    }
  } else {
    #pragma unroll
    for (int s4 = 0; s4 < 4; s4++){
      int idx = s4*256 + tid;
      int ii = idx >> 5, jj = idx & 31;
      if (jj > ii) o2[rowi + (size_t)ii*NN + jj] = prs[ii*33 + jj];
    }
    #pragma unroll
    for (int s4 = 0; s4 < 4; s4++){
      int idx = s4*256 + tid;
      int jj = idx >> 5, ii = idx & 31;
      if (jj > ii) o2[rowj + (size_t)jj*NN + ii] = prs[ii*33 + jj];
    }
    if (tid < 32) o2[rowi + (size_t)tid*NN + tid] = make_float2(0.f, 0.f);
  }
}

// ---------------- launch ----------------
extern "C" void kernel_launch(void* const* d_in, const int* in_sizes, int n_in,
                              void* d_out, int out_size){
  const float* nf  = (const float*)d_in[1];
  const float* W1  = (const float*)d_in[2];
  const float* b1  = (const float*)d_in[3];
  const float* g1  = (const float*)d_in[4];
  const float* be1 = (const float*)d_in[5];
  const float* W2  = (const float*)d_in[6];
  const float* b2  = (const float*)d_in[7];
  const float* g2  = (const float*)d_in[8];
  const float* be2 = (const float*)d_in[9];
  const float* W3  = (const float*)d_in[10];
  const float* b3  = (const float*)d_in[11];
  const float* W5  = (const float*)d_in[12];
  const float* b5  = (const float*)d_in[13];
  const float* g5  = (const float*)d_in[14];
  const float* be5 = (const float*)d_in[15];
  const float* W6  = (const float*)d_in[16];
  const float* b6  = (const float*)d_in[17];
  float* out = (float*)d_out;

  const int N2_SMEM = (HH*HH + 8*HH) * 4;
  cudaFuncSetAttribute(k_node2, cudaFuncAttributeMaxDynamicSharedMemorySize, N2_SMEM);
  cudaFuncSetAttribute(k_edgeG, cudaFuncAttributeMaxDynamicSharedMemorySize, EDGE1_SMEM);

  k_init<<<1, 128>>>();
  k_node1<<<256, 128>>>(nf, W1, b1);
  k_fold1<<<1, 128>>>(W2, b2, g1, be1);
  k_node2<<<256, 128, N2_SMEM>>>();
  k_fold2<<<1, 128>>>(W3, b3, g2, be2);
  k_node3<<<256, 128>>>(nf);
  k_edgeG<<<NPAIR, 256, EDGE1_SMEM>>>(W5, b5);
  k_stats<<<256, 256>>>();
  k_edge2h<<<NPAIR, 256>>>(W6, b6, g5, be5, out);
}